// round 1
// baseline (speedup 1.0000x reference)
#include <cuda_runtime.h>

typedef unsigned long long u64;

// ---------------- packed f32x2 primitives (sm_103a) ----------------
static __device__ __forceinline__ u64 pk(float lo, float hi) {
    u64 r; asm("mov.b64 %0, {%1, %2};" : "=l"(r) : "f"(lo), "f"(hi)); return r;
}
static __device__ __forceinline__ void upk(u64 v, float& lo, float& hi) {
    asm("mov.b64 {%0, %1}, %2;" : "=f"(lo), "=f"(hi) : "l"(v));
}
static __device__ __forceinline__ u64 ffma2(u64 a, u64 b, u64 c) {
    u64 d; asm("fma.rn.f32x2 %0, %1, %2, %3;" : "=l"(d) : "l"(a), "l"(b), "l"(c)); return d;
}
// accurate-enough tanh: 1 - 2/(e^{2x}+1); ex2.approx+rcp.approx, rel err ~1e-6
static __device__ __forceinline__ float tanh_fast(float x) {
    float e;   asm("ex2.approx.f32 %0, %1;" : "=f"(e)   : "f"(x * 2.885390081777927f)); // 2*log2(e)
    float rec; asm("rcp.approx.f32 %0, %1;" : "=f"(rec) : "f"(e + 1.0f));
    return fmaf(-2.0f, rec, 1.0f);
}
static __device__ __forceinline__ u64 tanh2(u64 v) {
    float a, b; upk(v, a, b);
    return pk(tanh_fast(a), tanh_fast(b));
}

// ---------------- shared-memory weight layout (u64 = {w,w} dup pairs) ----------------
static constexpr int OW1  = 0;            // 2*30
static constexpr int OB1  = OW1  + 60;    // 30
static constexpr int OW2  = OB1  + 30;    // 30*30
static constexpr int OB2  = OW2  + 900;   // 30
static constexpr int OW3  = OB2  + 30;    // 30*30
static constexpr int OB3  = OW3  + 900;   // 30
static constexpr int OW4  = OB3  + 30;    // 30*8
static constexpr int OB4  = OW4  + 240;   // 8
static constexpr int OP1  = OB4  + 8;     // 2*15
static constexpr int OPB1 = OP1  + 30;    // 15
static constexpr int OP2  = OPB1 + 15;    // 15*15
static constexpr int OPB2 = OP2  + 225;   // 15
static constexpr int OP3  = OPB2 + 15;    // 15*15
static constexpr int OPB3 = OP3  + 225;   // 15
static constexpr int OP4  = OPB3 + 15;    // 15*4
static constexpr int OPB4 = OP4  + 60;    // 4
static constexpr int SMW_TOTAL = OPB4 + 4; // 2787 u64 = 22296 B

// ---------------- dense layer: out[NO] = B + W^T in, all packed ----------------
template <int NI, int NO>
static __device__ __forceinline__ void dense(const u64* W, const u64* Bias,
                                             const u64* in, u64* out) {
#pragma unroll
    for (int j = 0; j < NO; j++) out[j] = Bias[j];
#pragma unroll
    for (int k = 0; k < NI; k++) {
        u64 hk = in[k];
#pragma unroll
        for (int j = 0; j < NO; j++) out[j] = ffma2(W[k * NO + j], hk, out[j]);
    }
}
template <int NN>
static __device__ __forceinline__ void tanh_all(u64* v) {
#pragma unroll
    for (int j = 0; j < NN; j++) v[j] = tanh2(v[j]);
}

// ---------------- half-angle: sin(θ/2), cos(θ/2) from cosθ, sinθ ----------------
static __device__ __forceinline__ void halfang(float c, float sn, float& sh, float& ch) {
    ch = sqrtf(fmaxf(0.0f, 0.5f * (1.0f + c)));
    float sh_a = copysignf(sqrtf(fmaxf(0.0f, 0.5f * (1.0f - c))), sn);
    float sh_b = __fdividef(0.5f * sn, ch);          // accurate when ch not tiny
    sh = (ch > 0.1f) ? sh_b : sh_a;
}

// ---------------- per-point epilogue (scalar; tiny vs MLP cost) ----------------
static __device__ __forceinline__ float epilogue(
    float x0, float x1, float r, float cb, float sb,
    const float* wv, const float* pv, float lm)
{
    // varphi at x: r0^k sin(kθ), k = 0.5, 1, 1.5
    float s2  = fmaf(x0, x0, x1 * x1);
    float ri0 = rsqrtf(s2);
    float r0  = s2 * ri0;
    float c   = x0 * ri0, sn = x1 * ri0;
    float sh, ch; halfang(c, sn, sh, ch);
    float sq  = sqrtf(r0);
    float v0  = sq * sh;
    float v1  = r0 * sn;
    float v2  = (r0 * sq) * fmaf(sn, ch, c * sh);
    // varphi at x_ba (unit vector): r0 = 1
    float shb, chb; halfang(cb, sb, shb, chb);
    float u0 = shb, u1 = sb, u2 = fmaf(sb, chb, cb * shb);
    // yita smoothstep
    float t  = fminf(fmaxf(fmaf(2.5f, r, -1.25f), 0.0f), 1.0f);
    float t3 = t * t * t;
    float yita = fmaf(fmaf(fmaf(-6.0f, t, 15.0f), t, -10.0f), t3, 1.0f);
    // combine
    float rp = wv[0] + yita * wv[4]
             + fmaf(wv[5], yita, wv[1]) * v0
             + fmaf(wv[6], yita, wv[2]) * v1
             + fmaf(wv[7], yita, wv[3]) * v2;
    float s  = fmaf(pv[1], u0, fmaf(pv[2], u1, fmaf(pv[3], u2, pv[0])));
    float sp = s * yita * __powf(r, lm);
    return rp + sp;
}

// ---------------- kernel: 2 points per thread, packed into f32x2 lanes ----------------
__global__ void __launch_bounds__(128)
mlp2d_kernel(const float* __restrict__ x,   const float* __restrict__ imv,
             const float* __restrict__ lmbd,
             const float* __restrict__ Ww1, const float* __restrict__ bw1,
             const float* __restrict__ Ww2, const float* __restrict__ bw2,
             const float* __restrict__ Ww3, const float* __restrict__ bw3,
             const float* __restrict__ Ww4, const float* __restrict__ bw4,
             const float* __restrict__ Wp1, const float* __restrict__ bp1,
             const float* __restrict__ Wp2, const float* __restrict__ bp2,
             const float* __restrict__ Wp3, const float* __restrict__ bp3,
             const float* __restrict__ Wp4, const float* __restrict__ bp4,
             float* __restrict__ out, int N)
{
    __shared__ u64   smw[SMW_TOTAL];
    __shared__ float scons[3];

    const int tid = threadIdx.x;
    // cooperative duplicated-pair weight load
    {
        const float* srcs[16] = {Ww1, bw1, Ww2, bw2, Ww3, bw3, Ww4, bw4,
                                 Wp1, bp1, Wp2, bp2, Wp3, bp3, Wp4, bp4};
        const int offs[17] = {OW1, OB1, OW2, OB2, OW3, OB3, OW4, OB4,
                              OP1, OPB1, OP2, OPB2, OP3, OPB3, OP4, OPB4, SMW_TOTAL};
#pragma unroll
        for (int a = 0; a < 16; a++) {
            const float* s = srcs[a];
            int base = offs[a], n = offs[a + 1] - offs[a];
            for (int t = tid; t < n; t += 128) {
                float w = s[t];
                smw[base + t] = pk(w, w);
            }
        }
        if (tid == 0) { scons[0] = imv[0]; scons[1] = imv[1]; scons[2] = lmbd[0]; }
    }
    __syncthreads();

    long long pair = (long long)blockIdx.x * 128 + tid;
    int i0 = (int)(2 * pair);
    if (i0 >= N) return;
    int i1 = (i0 + 1 < N) ? (i0 + 1) : i0;

    float2 pa = *(const float2*)(x + 2 * (size_t)i0);
    float2 pb = *(const float2*)(x + 2 * (size_t)i1);
    u64 X0 = pk(pa.x, pb.x);
    u64 X1 = pk(pa.y, pb.y);

    // ---- w-MLP: 2 -> 30 -> 30 -> 30 -> 8 (tanh on hidden) ----
    u64 A[30], B[30];
    {
        u64 xin[2] = {X0, X1};
        dense<2, 30>(smw + OW1, smw + OB1, xin, A);
    }
    tanh_all<30>(A);
    dense<30, 30>(smw + OW2, smw + OB2, A, B); tanh_all<30>(B);
    dense<30, 30>(smw + OW3, smw + OB3, B, A); tanh_all<30>(A);
    u64 Wo[8];
    dense<30, 8>(smw + OW4, smw + OB4, A, Wo);

    // ---- geometry about imv ----
    const float im0 = scons[0], im1 = scons[1], lm = scons[2];
    float xa0, xB0, xa1, xB1;
    upk(X0, xa0, xB0); upk(X1, xa1, xB1);

    float dA0 = xa0 - im0, dA1 = xa1 - im1;
    float rsA = fmaf(dA0, dA0, dA1 * dA1);
    float riA = rsqrtf(rsA);
    float rA  = rsA * riA;
    float cbA = dA0 * riA, sbA = dA1 * riA;

    float dB0 = xB0 - im0, dB1 = xB1 - im1;
    float rsB = fmaf(dB0, dB0, dB1 * dB1);
    float riB = rsqrtf(rsB);
    float rB  = rsB * riB;
    float cbB = dB0 * riB, sbB = dB1 * riB;

    // ---- phi-MLP: 2 -> 15 -> 15 -> 15 -> 4 on unit vectors ----
    u64 P_[15], Q_[15];
    {
        u64 xin[2] = {pk(cbA, cbB), pk(sbA, sbB)};
        dense<2, 15>(smw + OP1, smw + OPB1, xin, P_);
    }
    tanh_all<15>(P_);
    dense<15, 15>(smw + OP2, smw + OPB2, P_, Q_); tanh_all<15>(Q_);
    dense<15, 15>(smw + OP3, smw + OPB3, Q_, P_); tanh_all<15>(P_);
    u64 Ph[4];
    dense<15, 4>(smw + OP4, smw + OPB4, P_, Ph);

    // ---- unpack heads and finish per point ----
    float wA[8], wB[8], pA[4], pB[4];
#pragma unroll
    for (int j = 0; j < 8; j++) upk(Wo[j], wA[j], wB[j]);
#pragma unroll
    for (int j = 0; j < 4; j++) upk(Ph[j], pA[j], pB[j]);

    float eA = epilogue(xa0, xa1, rA, cbA, sbA, wA, pA, lm);
    out[i0] = eA;
    if (i1 != i0) {
        float eB = epilogue(xB0, xB1, rB, cbB, sbB, wB, pB, lm);
        out[i1] = eB;
    }
}

extern "C" void kernel_launch(void* const* d_in, const int* in_sizes, int n_in,
                              void* d_out, int out_size)
{
    const float* x    = (const float*)d_in[0];
    const float* imv  = (const float*)d_in[1];
    const float* lmbd = (const float*)d_in[2];
    const float* Ww1  = (const float*)d_in[3];
    const float* bw1  = (const float*)d_in[4];
    const float* Ww2  = (const float*)d_in[5];
    const float* bw2  = (const float*)d_in[6];
    const float* Ww3  = (const float*)d_in[7];
    const float* bw3  = (const float*)d_in[8];
    const float* Ww4  = (const float*)d_in[9];
    const float* bw4  = (const float*)d_in[10];
    const float* Wp1  = (const float*)d_in[11];
    const float* bp1  = (const float*)d_in[12];
    const float* Wp2  = (const float*)d_in[13];
    const float* bp2  = (const float*)d_in[14];
    const float* Wp3  = (const float*)d_in[15];
    const float* bp3  = (const float*)d_in[16];
    const float* Wp4  = (const float*)d_in[17];
    const float* bp4  = (const float*)d_in[18];

    int N = out_size;                    // one output per point
    long long pairs = ((long long)N + 1) / 2;
    int blocks = (int)((pairs + 127) / 128);

    mlp2d_kernel<<<blocks, 128>>>(x, imv, lmbd,
                                  Ww1, bw1, Ww2, bw2, Ww3, bw3, Ww4, bw4,
                                  Wp1, bp1, Wp2, bp2, Wp3, bp3, Wp4, bp4,
                                  (float*)d_out, N);
}